// round 3
// baseline (speedup 1.0000x reference)
#include <cuda_runtime.h>
#include <cuda_bf16.h>
#include <math.h>

// Shapes (fixed by the problem)
#define B_  8
#define C_  64
#define HID_ 256
#define H_  256
#define W_  256
#define HW_ (H_*W_)          // 65536
#define P_  4

// Scratch: FFN output y (B,C,H,W) and per-channel 4x4 circular kernels.
__device__ float g_y[B_ * C_ * HW_];      // 134 MB
__device__ float g_K[C_ * 16];            // 4 KB

// ---------------------------------------------------------------------------
// Kernel 1: build per-channel 4x4 circular-convolution kernel from cweight.
// out = irfft2( rfft2(y) * w ) (ortho)  ==  circular conv with
//   K[dp][dq] = (1/16) * sum_{u,v=0..3} Re( W_full[u,v] * e^{i*(pi/2)*(u*dp+v*dq)} )
// where W_full[u,v] = w[u][v] for v<3, and W_full[u][3] = conj(w[(4-u)%4][1]).
// cweight layout: (4, 3, 64, 2) row-major.
// ---------------------------------------------------------------------------
__global__ void prep_K_kernel(const float* __restrict__ cw) {
    int c = threadIdx.x;           // 64 threads
    if (c >= C_) return;

    float Wr[4][4], Wi[4][4];
#pragma unroll
    for (int u = 0; u < 4; u++) {
#pragma unroll
        for (int v = 0; v < 3; v++) {
            int o = ((u * 3 + v) * C_ + c) * 2;
            Wr[u][v] = cw[o];
            Wi[u][v] = cw[o + 1];
        }
        int mu = (4 - u) & 3;
        int o = ((mu * 3 + 1) * C_ + c) * 2;
        Wr[u][3] = cw[o];
        Wi[u][3] = -cw[o + 1];     // conjugate
    }

    const float ct[4] = {1.f, 0.f, -1.f, 0.f};
    const float st[4] = {0.f, 1.f, 0.f, -1.f};
#pragma unroll
    for (int dp = 0; dp < 4; dp++) {
#pragma unroll
        for (int dq = 0; dq < 4; dq++) {
            float s = 0.f;
#pragma unroll
            for (int u = 0; u < 4; u++) {
#pragma unroll
                for (int v = 0; v < 4; v++) {
                    int m = (u * dp + v * dq) & 3;
                    s += Wr[u][v] * ct[m] - Wi[u][v] * st[m];
                }
            }
            g_K[c * 16 + dp * 4 + dq] = s * (1.f / 16.f);
        }
    }
}

// ---------------------------------------------------------------------------
// Kernel 2: fused FFN. For each pixel: h = gelu(W1 x + b1); y = W2 h + b2.
// Thread-per-pixel: x[64], acc[64] in registers; W1 (256x64) and W2^T (256x64)
// in shared memory, read via broadcast LDS.128. Block = 256 contiguous pixels
// of one batch image.
// ---------------------------------------------------------------------------
__global__ void __launch_bounds__(256, 1)
ffn_kernel(const float* __restrict__ x,
           const float* __restrict__ w1,
           const float* __restrict__ b1,
           const float* __restrict__ w2,
           const float* __restrict__ b2) {
    extern __shared__ float sm[];
    float* w1s = sm;                 // [256][64]
    float* w2t = sm + 16384;         // [256][64]  (transposed W2)
    float* b1s = sm + 32768;         // [256]
    float* b2s = sm + 33024;         // [64]

    const int tid = threadIdx.x;

    for (int i = tid; i < HID_ * C_; i += 256) w1s[i] = w1[i];
    for (int i = tid; i < HID_ * C_; i += 256) {
        int j = i >> 6, o = i & 63;
        w2t[i] = w2[o * HID_ + j];
    }
    b1s[tid] = b1[tid];
    if (tid < C_) b2s[tid] = b2[tid];
    __syncthreads();

    const int blk   = blockIdx.x;
    const int b     = blk >> 8;        // 256 chunks per batch
    const int chunk = blk & 255;
    const int pix   = (chunk << 8) + tid;
    const int gbase = (b << 22) + pix; // b*C*HW + pix

    // Load the pixel's 64 input channels (coalesced per channel across warp).
    float xr[64];
#pragma unroll
    for (int k = 0; k < 64; k++) xr[k] = __ldg(x + gbase + (k << 16));

    float acc[64];
#pragma unroll
    for (int c = 0; c < 64; c++) acc[c] = 0.f;

#pragma unroll 1
    for (int j = 0; j < HID_; j++) {
        const float4* wv = reinterpret_cast<const float4*>(w1s + (j << 6));
        float h0 = 0.f, h1 = 0.f, h2 = 0.f, h3 = 0.f;
#pragma unroll
        for (int kk = 0; kk < 16; kk++) {
            float4 w = wv[kk];
            h0 = fmaf(w.x, xr[kk * 4 + 0], h0);
            h1 = fmaf(w.y, xr[kk * 4 + 1], h1);
            h2 = fmaf(w.z, xr[kk * 4 + 2], h2);
            h3 = fmaf(w.w, xr[kk * 4 + 3], h3);
        }
        float h = ((h0 + h1) + (h2 + h3)) + b1s[j];
        // exact GELU: 0.5*h*(1+erf(h/sqrt(2)))
        float g = 0.5f * h * (1.0f + erff(h * 0.70710678118654752f));

        const float4* w2v = reinterpret_cast<const float4*>(w2t + (j << 6));
#pragma unroll
        for (int cc = 0; cc < 16; cc++) {
            float4 w = w2v[cc];
            acc[cc * 4 + 0] = fmaf(w.x, g, acc[cc * 4 + 0]);
            acc[cc * 4 + 1] = fmaf(w.y, g, acc[cc * 4 + 1]);
            acc[cc * 4 + 2] = fmaf(w.z, g, acc[cc * 4 + 2]);
            acc[cc * 4 + 3] = fmaf(w.w, g, acc[cc * 4 + 3]);
        }
    }

    float* yb = g_y + gbase;
#pragma unroll
    for (int c = 0; c < 64; c++) yb[c << 16] = acc[c] + b2s[c];
}

// ---------------------------------------------------------------------------
// Kernel 3: per-window 4x4 circular convolution with K_c.
// One thread = one full 4x4 window (16 loads, 256 FMA, 16 stores), float4 I/O.
// ---------------------------------------------------------------------------
__global__ void __launch_bounds__(256)
winconv_kernel(float* __restrict__ out) {
    const int idx = blockIdx.x * 256 + threadIdx.x;   // window id
    const int wx = idx & 63;
    const int wy = (idx >> 6) & 63;
    const int c  = (idx >> 12) & 63;
    const int b  = idx >> 18;

    __shared__ float Ks[16];
    if (threadIdx.x < 16) Ks[threadIdx.x] = g_K[(c << 4) + threadIdx.x];  // c uniform per block
    __syncthreads();

    float kr[16];
#pragma unroll
    for (int i = 0; i < 16; i++) kr[i] = Ks[i];

    const int base = (((b << 6) + c) << 16) + (wy << 2) * W_ + (wx << 2);
    const float* yp = g_y + base;

    float4 r0 = *reinterpret_cast<const float4*>(yp);
    float4 r1 = *reinterpret_cast<const float4*>(yp + W_);
    float4 r2 = *reinterpret_cast<const float4*>(yp + 2 * W_);
    float4 r3 = *reinterpret_cast<const float4*>(yp + 3 * W_);
    const float vv[16] = {r0.x, r0.y, r0.z, r0.w,
                          r1.x, r1.y, r1.z, r1.w,
                          r2.x, r2.y, r2.z, r2.w,
                          r3.x, r3.y, r3.z, r3.w};

#pragma unroll
    for (int ro = 0; ro < 4; ro++) {
        float o0 = 0.f, o1 = 0.f, o2 = 0.f, o3 = 0.f;
#pragma unroll
        for (int r = 0; r < 4; r++) {
            const int dp4 = ((ro - r) & 3) * 4;
#pragma unroll
            for (int s = 0; s < 4; s++) {
                const float v = vv[r * 4 + s];
                o0 = fmaf(kr[dp4 + ((0 - s) & 3)], v, o0);
                o1 = fmaf(kr[dp4 + ((1 - s) & 3)], v, o1);
                o2 = fmaf(kr[dp4 + ((2 - s) & 3)], v, o2);
                o3 = fmaf(kr[dp4 + ((3 - s) & 3)], v, o3);
            }
        }
        *reinterpret_cast<float4*>(out + base + ro * W_) = make_float4(o0, o1, o2, o3);
    }
}

// ---------------------------------------------------------------------------
extern "C" void kernel_launch(void* const* d_in, const int* in_sizes, int n_in,
                              void* d_out, int out_size) {
    const float* x  = (const float*)d_in[0];
    const float* w1 = (const float*)d_in[1];
    const float* b1 = (const float*)d_in[2];
    const float* w2 = (const float*)d_in[3];
    const float* b2 = (const float*)d_in[4];
    const float* cw = (const float*)d_in[5];
    float* out = (float*)d_out;

    const int smem_bytes = (16384 + 16384 + 256 + 64) * (int)sizeof(float); // 132352
    cudaFuncSetAttribute(ffn_kernel, cudaFuncAttributeMaxDynamicSharedMemorySize, smem_bytes);

    prep_K_kernel<<<1, 64>>>(cw);
    ffn_kernel<<<B_ * 256, 256, smem_bytes>>>(x, w1, b1, w2, b2);
    // windows: B * C * (H/4) * (W/4) = 2,097,152 -> 8192 blocks of 256
    winconv_kernel<<<(B_ * C_ * (H_ / P_) * (W_ / P_)) / 256, 256>>>(out);
}

// round 4
// speedup vs baseline: 1.0002x; 1.0002x over previous
#include <cuda_runtime.h>
#include <cuda_bf16.h>
#include <math.h>

// Shapes (fixed by the problem)
#define B_  8
#define C_  64
#define HID_ 256
#define H_  256
#define W_  256
#define HW_ (H_*W_)          // 65536
#define P_  4

// Scratch: FFN output y (B,C,H,W) and per-channel 4x4 circular kernels.
__device__ float g_y[B_ * C_ * HW_];      // 134 MB
__device__ float g_K[C_ * 16];            // 4 KB

// ---------------------------------------------------------------------------
// Kernel 1: build per-channel 4x4 circular-convolution kernel from cweight.
// out = irfft2( rfft2(y) * w ) (ortho)  ==  circular conv with
//   K[dp][dq] = (1/16) * sum_{u,v=0..3} Re( W_full[u,v] * e^{i*(pi/2)*(u*dp+v*dq)} )
// where W_full[u,v] = w[u][v] for v<3, and W_full[u][3] = conj(w[(4-u)%4][1]).
// cweight layout: (4, 3, 64, 2) row-major.
// ---------------------------------------------------------------------------
__global__ void prep_K_kernel(const float* __restrict__ cw) {
    int c = threadIdx.x;           // 64 threads
    if (c >= C_) return;

    float Wr[4][4], Wi[4][4];
#pragma unroll
    for (int u = 0; u < 4; u++) {
#pragma unroll
        for (int v = 0; v < 3; v++) {
            int o = ((u * 3 + v) * C_ + c) * 2;
            Wr[u][v] = cw[o];
            Wi[u][v] = cw[o + 1];
        }
        int mu = (4 - u) & 3;
        int o = ((mu * 3 + 1) * C_ + c) * 2;
        Wr[u][3] = cw[o];
        Wi[u][3] = -cw[o + 1];     // conjugate
    }

    const float ct[4] = {1.f, 0.f, -1.f, 0.f};
    const float st[4] = {0.f, 1.f, 0.f, -1.f};
#pragma unroll
    for (int dp = 0; dp < 4; dp++) {
#pragma unroll
        for (int dq = 0; dq < 4; dq++) {
            float s = 0.f;
#pragma unroll
            for (int u = 0; u < 4; u++) {
#pragma unroll
                for (int v = 0; v < 4; v++) {
                    int m = (u * dp + v * dq) & 3;
                    s += Wr[u][v] * ct[m] - Wi[u][v] * st[m];
                }
            }
            g_K[c * 16 + dp * 4 + dq] = s * (1.f / 16.f);
        }
    }
}

// ---------------------------------------------------------------------------
// Kernel 2: fused FFN. For each pixel: h = gelu(W1 x + b1); y = W2 h + b2.
// Thread-per-pixel: x[64], acc[64] in registers; W1 (256x64) and W2^T (256x64)
// in shared memory, read via broadcast LDS.128. Block = 256 contiguous pixels
// of one batch image.
// ---------------------------------------------------------------------------
__global__ void __launch_bounds__(256, 1)
ffn_kernel(const float* __restrict__ x,
           const float* __restrict__ w1,
           const float* __restrict__ b1,
           const float* __restrict__ w2,
           const float* __restrict__ b2) {
    extern __shared__ float sm[];
    float* w1s = sm;                 // [256][64]
    float* w2t = sm + 16384;         // [256][64]  (transposed W2)
    float* b1s = sm + 32768;         // [256]
    float* b2s = sm + 33024;         // [64]

    const int tid = threadIdx.x;

    for (int i = tid; i < HID_ * C_; i += 256) w1s[i] = w1[i];
    for (int i = tid; i < HID_ * C_; i += 256) {
        int j = i >> 6, o = i & 63;
        w2t[i] = w2[o * HID_ + j];
    }
    b1s[tid] = b1[tid];
    if (tid < C_) b2s[tid] = b2[tid];
    __syncthreads();

    const int blk   = blockIdx.x;
    const int b     = blk >> 8;        // 256 chunks per batch
    const int chunk = blk & 255;
    const int pix   = (chunk << 8) + tid;
    const int gbase = (b << 22) + pix; // b*C*HW + pix

    // Load the pixel's 64 input channels (coalesced per channel across warp).
    float xr[64];
#pragma unroll
    for (int k = 0; k < 64; k++) xr[k] = __ldg(x + gbase + (k << 16));

    float acc[64];
#pragma unroll
    for (int c = 0; c < 64; c++) acc[c] = 0.f;

#pragma unroll 1
    for (int j = 0; j < HID_; j++) {
        const float4* wv = reinterpret_cast<const float4*>(w1s + (j << 6));
        float h0 = 0.f, h1 = 0.f, h2 = 0.f, h3 = 0.f;
#pragma unroll
        for (int kk = 0; kk < 16; kk++) {
            float4 w = wv[kk];
            h0 = fmaf(w.x, xr[kk * 4 + 0], h0);
            h1 = fmaf(w.y, xr[kk * 4 + 1], h1);
            h2 = fmaf(w.z, xr[kk * 4 + 2], h2);
            h3 = fmaf(w.w, xr[kk * 4 + 3], h3);
        }
        float h = ((h0 + h1) + (h2 + h3)) + b1s[j];
        // exact GELU: 0.5*h*(1+erf(h/sqrt(2)))
        float g = 0.5f * h * (1.0f + erff(h * 0.70710678118654752f));

        const float4* w2v = reinterpret_cast<const float4*>(w2t + (j << 6));
#pragma unroll
        for (int cc = 0; cc < 16; cc++) {
            float4 w = w2v[cc];
            acc[cc * 4 + 0] = fmaf(w.x, g, acc[cc * 4 + 0]);
            acc[cc * 4 + 1] = fmaf(w.y, g, acc[cc * 4 + 1]);
            acc[cc * 4 + 2] = fmaf(w.z, g, acc[cc * 4 + 2]);
            acc[cc * 4 + 3] = fmaf(w.w, g, acc[cc * 4 + 3]);
        }
    }

    float* yb = g_y + gbase;
#pragma unroll
    for (int c = 0; c < 64; c++) yb[c << 16] = acc[c] + b2s[c];
}

// ---------------------------------------------------------------------------
// Kernel 3: per-window 4x4 circular convolution with K_c.
// One thread = one full 4x4 window (16 loads, 256 FMA, 16 stores), float4 I/O.
// ---------------------------------------------------------------------------
__global__ void __launch_bounds__(256)
winconv_kernel(float* __restrict__ out) {
    const int idx = blockIdx.x * 256 + threadIdx.x;   // window id
    const int wx = idx & 63;
    const int wy = (idx >> 6) & 63;
    const int c  = (idx >> 12) & 63;
    const int b  = idx >> 18;

    __shared__ float Ks[16];
    if (threadIdx.x < 16) Ks[threadIdx.x] = g_K[(c << 4) + threadIdx.x];  // c uniform per block
    __syncthreads();

    float kr[16];
#pragma unroll
    for (int i = 0; i < 16; i++) kr[i] = Ks[i];

    const int base = (((b << 6) + c) << 16) + (wy << 2) * W_ + (wx << 2);
    const float* yp = g_y + base;

    float4 r0 = *reinterpret_cast<const float4*>(yp);
    float4 r1 = *reinterpret_cast<const float4*>(yp + W_);
    float4 r2 = *reinterpret_cast<const float4*>(yp + 2 * W_);
    float4 r3 = *reinterpret_cast<const float4*>(yp + 3 * W_);
    const float vv[16] = {r0.x, r0.y, r0.z, r0.w,
                          r1.x, r1.y, r1.z, r1.w,
                          r2.x, r2.y, r2.z, r2.w,
                          r3.x, r3.y, r3.z, r3.w};

#pragma unroll
    for (int ro = 0; ro < 4; ro++) {
        float o0 = 0.f, o1 = 0.f, o2 = 0.f, o3 = 0.f;
#pragma unroll
        for (int r = 0; r < 4; r++) {
            const int dp4 = ((ro - r) & 3) * 4;
#pragma unroll
            for (int s = 0; s < 4; s++) {
                const float v = vv[r * 4 + s];
                o0 = fmaf(kr[dp4 + ((0 - s) & 3)], v, o0);
                o1 = fmaf(kr[dp4 + ((1 - s) & 3)], v, o1);
                o2 = fmaf(kr[dp4 + ((2 - s) & 3)], v, o2);
                o3 = fmaf(kr[dp4 + ((3 - s) & 3)], v, o3);
            }
        }
        *reinterpret_cast<float4*>(out + base + ro * W_) = make_float4(o0, o1, o2, o3);
    }
}

// ---------------------------------------------------------------------------
extern "C" void kernel_launch(void* const* d_in, const int* in_sizes, int n_in,
                              void* d_out, int out_size) {
    const float* x  = (const float*)d_in[0];
    const float* w1 = (const float*)d_in[1];
    const float* b1 = (const float*)d_in[2];
    const float* w2 = (const float*)d_in[3];
    const float* b2 = (const float*)d_in[4];
    const float* cw = (const float*)d_in[5];
    float* out = (float*)d_out;

    const int smem_bytes = (16384 + 16384 + 256 + 64) * (int)sizeof(float); // 132352
    cudaFuncSetAttribute(ffn_kernel, cudaFuncAttributeMaxDynamicSharedMemorySize, smem_bytes);

    prep_K_kernel<<<1, 64>>>(cw);
    ffn_kernel<<<B_ * 256, 256, smem_bytes>>>(x, w1, b1, w2, b2);
    // windows: B * C * (H/4) * (W/4) = 2,097,152 -> 8192 blocks of 256
    winconv_kernel<<<(B_ * C_ * (H_ / P_) * (W_ / P_)) / 256, 256>>>(out);
}

// round 5
// speedup vs baseline: 1.0991x; 1.0990x over previous
#include <cuda_runtime.h>
#include <cuda_bf16.h>
#include <math.h>

// Shapes (fixed by the problem)
#define B_  8
#define C_  64
#define HID_ 256
#define H_  256
#define W_  256
#define HW_ (H_*W_)          // 65536
#define P_  4

// Scratch: FFN output y (B,C,H,W) and per-channel 4x4 circular kernels.
__device__ float g_y[B_ * C_ * HW_];      // 134 MB
__device__ float g_K[C_ * 16];            // 4 KB

// ---------------------------------------------------------------------------
// Kernel 1: build per-channel 4x4 circular-convolution kernel from cweight.
// (unchanged from R3 — verified correct)
// ---------------------------------------------------------------------------
__global__ void prep_K_kernel(const float* __restrict__ cw) {
    int c = threadIdx.x;           // 64 threads
    if (c >= C_) return;

    float Wr[4][4], Wi[4][4];
#pragma unroll
    for (int u = 0; u < 4; u++) {
#pragma unroll
        for (int v = 0; v < 3; v++) {
            int o = ((u * 3 + v) * C_ + c) * 2;
            Wr[u][v] = cw[o];
            Wi[u][v] = cw[o + 1];
        }
        int mu = (4 - u) & 3;
        int o = ((mu * 3 + 1) * C_ + c) * 2;
        Wr[u][3] = cw[o];
        Wi[u][3] = -cw[o + 1];     // conjugate
    }

    const float ct[4] = {1.f, 0.f, -1.f, 0.f};
    const float st[4] = {0.f, 1.f, 0.f, -1.f};
#pragma unroll
    for (int dp = 0; dp < 4; dp++) {
#pragma unroll
        for (int dq = 0; dq < 4; dq++) {
            float s = 0.f;
#pragma unroll
            for (int u = 0; u < 4; u++) {
#pragma unroll
                for (int v = 0; v < 4; v++) {
                    int m = (u * dp + v * dq) & 3;
                    s += Wr[u][v] * ct[m] - Wi[u][v] * st[m];
                }
            }
            g_K[c * 16 + dp * 4 + dq] = s * (1.f / 16.f);
        }
    }
}

// ---------------------------------------------------------------------------
// f32x2 helpers (sm_103a packed fp32 FMA — FFMA2 in SASS, 2x fma-pipe rate)
// ---------------------------------------------------------------------------
__device__ __forceinline__ unsigned long long pack_f32x2(float lo, float hi) {
    unsigned long long r;
    asm("mov.b64 %0, {%1, %2};" : "=l"(r) : "f"(lo), "f"(hi));
    return r;
}
__device__ __forceinline__ void unpack_f32x2(unsigned long long p, float& lo, float& hi) {
    asm("mov.b64 {%0, %1}, %2;" : "=f"(lo), "=f"(hi) : "l"(p));
}
#define FMA2(d, a, b, c) \
    asm("fma.rn.f32x2 %0, %1, %2, %3;" : "=l"(d) : "l"(a), "l"(b), "l"(c))
#define LDS_V2B64(p0, p1, addr) \
    asm volatile("ld.shared.v2.b64 {%0, %1}, [%2];" : "=l"(p0), "=l"(p1) : "r"(addr))

// ---------------------------------------------------------------------------
// Kernel 2: fused FFN using packed f32x2 FMAs.
// Thread-per-pixel: x packed in 32 f32x2 regs, acc in 32 f32x2 regs.
// W1 (256x64) and W2^T (256x64) in smem, read as ld.shared.v2.b64 (broadcast)
// so each 64-bit half lands in an aligned register pair directly usable as
// an fma.rn.f32x2 operand — no packing MOVs in the hot loop.
// ---------------------------------------------------------------------------
__global__ void __launch_bounds__(256, 1)
ffn_kernel(const float* __restrict__ x,
           const float* __restrict__ w1,
           const float* __restrict__ b1,
           const float* __restrict__ w2,
           const float* __restrict__ b2) {
    extern __shared__ float sm[];
    float* w1s = sm;                 // [256][64]
    float* w2t = sm + 16384;         // [256][64]  (transposed W2)
    float* b1s = sm + 32768;         // [256]
    float* b2s = sm + 33024;         // [64]

    const int tid = threadIdx.x;

    for (int i = tid; i < HID_ * C_; i += 256) w1s[i] = w1[i];
    for (int i = tid; i < HID_ * C_; i += 256) {
        int j = i >> 6, o = i & 63;
        w2t[i] = w2[o * HID_ + j];
    }
    b1s[tid] = b1[tid];
    if (tid < C_) b2s[tid] = b2[tid];
    __syncthreads();

    const unsigned w1a = (unsigned)__cvta_generic_to_shared(w1s);
    const unsigned w2a = (unsigned)__cvta_generic_to_shared(w2t);

    const int blk   = blockIdx.x;
    const int b     = blk >> 8;        // 256 chunks per batch
    const int chunk = blk & 255;
    const int pix   = (chunk << 8) + tid;
    const int gbase = (b << 22) + pix; // b*C*HW + pix

    // Load the pixel's 64 input channels, packed into 32 f32x2 pairs.
    unsigned long long xp[32];
#pragma unroll
    for (int k = 0; k < 32; k++) {
        float a = __ldg(x + gbase + ((2 * k) << 16));
        float c = __ldg(x + gbase + ((2 * k + 1) << 16));
        xp[k] = pack_f32x2(a, c);
    }

    unsigned long long accp[32];
#pragma unroll
    for (int i = 0; i < 32; i++) accp[i] = 0ULL;   // (+0.f, +0.f)

#pragma unroll 1
    for (int j = 0; j < HID_; j++) {
        const unsigned a1 = w1a + (j << 8);
        unsigned long long h0 = 0ULL, h1 = 0ULL, h2 = 0ULL, h3 = 0ULL;
#pragma unroll
        for (int kk = 0; kk < 16; kk += 2) {
            unsigned long long p0, p1, p2, p3;
            LDS_V2B64(p0, p1, a1 + kk * 16);
            LDS_V2B64(p2, p3, a1 + kk * 16 + 16);
            FMA2(h0, p0, xp[2 * kk + 0], h0);
            FMA2(h1, p1, xp[2 * kk + 1], h1);
            FMA2(h2, p2, xp[2 * kk + 2], h2);
            FMA2(h3, p3, xp[2 * kk + 3], h3);
        }
        float s0, s1, s2, s3, s4, s5, s6, s7;
        unpack_f32x2(h0, s0, s1);
        unpack_f32x2(h1, s2, s3);
        unpack_f32x2(h2, s4, s5);
        unpack_f32x2(h3, s6, s7);
        float h = (((s0 + s1) + (s2 + s3)) + ((s4 + s5) + (s6 + s7))) + b1s[j];
        // exact GELU: 0.5*h*(1+erf(h/sqrt(2)))
        float g = 0.5f * h * (1.0f + erff(h * 0.70710678118654752f));
        const unsigned long long gp = pack_f32x2(g, g);

        const unsigned a2 = w2a + (j << 8);
#pragma unroll
        for (int kk = 0; kk < 16; kk++) {
            unsigned long long q0, q1;
            LDS_V2B64(q0, q1, a2 + kk * 16);
            FMA2(accp[2 * kk + 0], q0, gp, accp[2 * kk + 0]);
            FMA2(accp[2 * kk + 1], q1, gp, accp[2 * kk + 1]);
        }
    }

    float* yb = g_y + gbase;
#pragma unroll
    for (int i = 0; i < 32; i++) {
        float lo, hi;
        unpack_f32x2(accp[i], lo, hi);
        yb[(2 * i) << 16]     = lo + b2s[2 * i];
        yb[(2 * i + 1) << 16] = hi + b2s[2 * i + 1];
    }
}

// ---------------------------------------------------------------------------
// Kernel 3: per-window 4x4 circular convolution with K_c.
// (unchanged from R3 — verified correct, ~45 µs, near memory roofline)
// ---------------------------------------------------------------------------
__global__ void __launch_bounds__(256)
winconv_kernel(float* __restrict__ out) {
    const int idx = blockIdx.x * 256 + threadIdx.x;   // window id
    const int wx = idx & 63;
    const int wy = (idx >> 6) & 63;
    const int c  = (idx >> 12) & 63;
    const int b  = idx >> 18;

    __shared__ float Ks[16];
    if (threadIdx.x < 16) Ks[threadIdx.x] = g_K[(c << 4) + threadIdx.x];  // c uniform per block
    __syncthreads();

    float kr[16];
#pragma unroll
    for (int i = 0; i < 16; i++) kr[i] = Ks[i];

    const int base = (((b << 6) + c) << 16) + (wy << 2) * W_ + (wx << 2);
    const float* yp = g_y + base;

    float4 r0 = *reinterpret_cast<const float4*>(yp);
    float4 r1 = *reinterpret_cast<const float4*>(yp + W_);
    float4 r2 = *reinterpret_cast<const float4*>(yp + 2 * W_);
    float4 r3 = *reinterpret_cast<const float4*>(yp + 3 * W_);
    const float vv[16] = {r0.x, r0.y, r0.z, r0.w,
                          r1.x, r1.y, r1.z, r1.w,
                          r2.x, r2.y, r2.z, r2.w,
                          r3.x, r3.y, r3.z, r3.w};

#pragma unroll
    for (int ro = 0; ro < 4; ro++) {
        float o0 = 0.f, o1 = 0.f, o2 = 0.f, o3 = 0.f;
#pragma unroll
        for (int r = 0; r < 4; r++) {
            const int dp4 = ((ro - r) & 3) * 4;
#pragma unroll
            for (int s = 0; s < 4; s++) {
                const float v = vv[r * 4 + s];
                o0 = fmaf(kr[dp4 + ((0 - s) & 3)], v, o0);
                o1 = fmaf(kr[dp4 + ((1 - s) & 3)], v, o1);
                o2 = fmaf(kr[dp4 + ((2 - s) & 3)], v, o2);
                o3 = fmaf(kr[dp4 + ((3 - s) & 3)], v, o3);
            }
        }
        *reinterpret_cast<float4*>(out + base + ro * W_) = make_float4(o0, o1, o2, o3);
    }
}

// ---------------------------------------------------------------------------
extern "C" void kernel_launch(void* const* d_in, const int* in_sizes, int n_in,
                              void* d_out, int out_size) {
    const float* x  = (const float*)d_in[0];
    const float* w1 = (const float*)d_in[1];
    const float* b1 = (const float*)d_in[2];
    const float* w2 = (const float*)d_in[3];
    const float* b2 = (const float*)d_in[4];
    const float* cw = (const float*)d_in[5];
    float* out = (float*)d_out;

    const int smem_bytes = (16384 + 16384 + 256 + 64) * (int)sizeof(float); // 132352
    cudaFuncSetAttribute(ffn_kernel, cudaFuncAttributeMaxDynamicSharedMemorySize, smem_bytes);

    prep_K_kernel<<<1, 64>>>(cw);
    ffn_kernel<<<B_ * 256, 256, smem_bytes>>>(x, w1, b1, w2, b2);
    // windows: B * C * (H/4) * (W/4) = 2,097,152 -> 8192 blocks of 256
    winconv_kernel<<<(B_ * C_ * (H_ / P_) * (W_ / P_)) / 256, 256>>>(out);
}

// round 6
// speedup vs baseline: 1.2689x; 1.1545x over previous
#include <cuda_runtime.h>
#include <cuda_bf16.h>
#include <math.h>

// Shapes (fixed by the problem)
#define B_  8
#define C_  64
#define HID_ 256
#define H_  256
#define W_  256
#define HW_ (H_*W_)          // 65536
#define P_  4

#define NTILES 4096          // 524288 pixels / 128 per tile
#define TILE_P 128

// Scratch: FFN output y (B,C,H,W) and per-channel 4x4 circular kernels.
__device__ float g_y[B_ * C_ * HW_];      // 134 MB
__device__ float g_K[C_ * 16];            // 4 KB

// ---------------------------------------------------------------------------
// Kernel 1: build per-channel 4x4 circular-convolution kernel from cweight.
// (unchanged — verified correct)
// ---------------------------------------------------------------------------
__global__ void prep_K_kernel(const float* __restrict__ cw) {
    int c = threadIdx.x;           // 64 threads
    if (c >= C_) return;

    float Wr[4][4], Wi[4][4];
#pragma unroll
    for (int u = 0; u < 4; u++) {
#pragma unroll
        for (int v = 0; v < 3; v++) {
            int o = ((u * 3 + v) * C_ + c) * 2;
            Wr[u][v] = cw[o];
            Wi[u][v] = cw[o + 1];
        }
        int mu = (4 - u) & 3;
        int o = ((mu * 3 + 1) * C_ + c) * 2;
        Wr[u][3] = cw[o];
        Wi[u][3] = -cw[o + 1];     // conjugate
    }

    const float ct[4] = {1.f, 0.f, -1.f, 0.f};
    const float st[4] = {0.f, 1.f, 0.f, -1.f};
#pragma unroll
    for (int dp = 0; dp < 4; dp++) {
#pragma unroll
        for (int dq = 0; dq < 4; dq++) {
            float s = 0.f;
#pragma unroll
            for (int u = 0; u < 4; u++) {
#pragma unroll
                for (int v = 0; v < 4; v++) {
                    int m = (u * dp + v * dq) & 3;
                    s += Wr[u][v] * ct[m] - Wi[u][v] * st[m];
                }
            }
            g_K[c * 16 + dp * 4 + dq] = s * (1.f / 16.f);
        }
    }
}

// ---------------------------------------------------------------------------
// f32x2 helpers (sm_103a packed fp32 FMA — FFMA2 in SASS)
// ---------------------------------------------------------------------------
__device__ __forceinline__ unsigned long long pack2(float lo, float hi) {
    unsigned long long r;
    asm("mov.b64 %0, {%1, %2};" : "=l"(r) : "f"(lo), "f"(hi));
    return r;
}
__device__ __forceinline__ void unpack2(unsigned long long p, float& lo, float& hi) {
    asm("mov.b64 {%0, %1}, %2;" : "=f"(lo), "=f"(hi) : "l"(p));
}
#define FMA2(d, a, b, c) \
    asm("fma.rn.f32x2 %0, %1, %2, %3;" : "=l"(d) : "l"(a), "l"(b), "l"(c))

__device__ __forceinline__ float gelu_exact(float h) {
    return 0.5f * h * (1.0f + erff(h * 0.70710678118654752f));
}

// ---------------------------------------------------------------------------
// Kernel 2: fused FFN as a register-blocked tiled SGEMM chain.
// Persistent blocks (grid=148). Per 128-pixel tile:
//   GEMM1 (j-half of 128): each thread -> 8j x 8p accumulators (f32x2)
//   GELU + bias -> H half-tile in smem
//   GEMM2: each thread -> 4c x 8p accumulators, k accumulated across halves
// smem: W1T [64k][256j] + W2T [256k][64c] + X [64k][128p] + H [128j][128p]
// ---------------------------------------------------------------------------
__global__ void __launch_bounds__(256, 1)
ffn_kernel(const float* __restrict__ x,
           const float* __restrict__ w1,
           const float* __restrict__ b1,
           const float* __restrict__ w2,
           const float* __restrict__ b2) {
    extern __shared__ float sm[];
    float* w1t = sm;              // [64][256]   64 KB  row=1024B
    float* w2t = sm + 16384;      // [256][64]   64 KB  row=256B
    float* xs  = sm + 32768;      // [64][128]   32 KB  row=512B
    float* hs  = sm + 40960;      // [128][128]  64 KB  row=512B
    float* b1s = sm + 57344;      // [256]
    float* b2s = sm + 57600;      // [64]

    const int tid = threadIdx.x;

    // Load weights transposed (write-coalesced; one-time cost per block).
    for (int i = tid; i < 16384; i += 256) {
        int k = i >> 8, j = i & 255;
        w1t[i] = w1[j * 64 + k];           // w1t[k][j]
    }
    for (int i = tid; i < 16384; i += 256) {
        int k = i >> 6, c = i & 63;
        w2t[i] = w2[c * 256 + k];          // w2t[k][c]
    }
    b1s[tid] = b1[tid];
    if (tid < 64) b2s[tid] = b2[tid];

    const int g1 = tid >> 4;   // 0..15 : j-group (GEMM1) / c-group (GEMM2)
    const int g2 = tid & 15;   // 0..15 : pixel-group (8 pixels)

    const unsigned s_w1 = (unsigned)__cvta_generic_to_shared(w1t);
    const unsigned s_w2 = (unsigned)__cvta_generic_to_shared(w2t);
    const unsigned s_x  = (unsigned)__cvta_generic_to_shared(xs);
    const unsigned s_h  = (unsigned)__cvta_generic_to_shared(hs);

    for (int tile = blockIdx.x; tile < NTILES; tile += gridDim.x) {
        const int b = tile >> 9;                  // 512 tiles per batch image
        const int pixbase = (tile & 511) << 7;
        const float* xb = x + (b << 22) + pixbase;

        __syncthreads();
        // Load X tile [64][128] (coalesced float4)
#pragma unroll
        for (int r = 0; r < 8; r++) {
            int idx = r * 1024 + tid * 4;
            int k = idx >> 7, p = idx & 127;
            float4 v = *reinterpret_cast<const float4*>(xb + (k << 16) + p);
            *reinterpret_cast<float4*>(xs + idx) = v;
        }

        unsigned long long acc2[16];              // 4c x 4 pixel-pairs
#pragma unroll
        for (int i = 0; i < 16; i++) acc2[i] = 0ULL;

#pragma unroll 1
        for (int half = 0; half < 2; half++) {
            __syncthreads();   // X ready (half0) / hs consumed by GEMM2 (half1)

            // ---- GEMM1: h[j] for j in [half*128 + g1*8, +8), p in [g2*8, +8)
            unsigned long long acc1[32];          // 8j x 4 pixel-pairs
#pragma unroll
            for (int i = 0; i < 32; i++) acc1[i] = 0ULL;

            const unsigned wb = s_w1 + (unsigned)(((half << 7) + (g1 << 3)) << 2);
            const unsigned xb1 = s_x + (unsigned)((g2 << 3) << 2);
#pragma unroll 4
            for (int k = 0; k < 64; k++) {
                float a0, a1, a2, a3, a4, a5, a6, a7;
                asm volatile("ld.shared.v4.f32 {%0,%1,%2,%3}, [%4];"
                             : "=f"(a0), "=f"(a1), "=f"(a2), "=f"(a3)
                             : "r"(wb + k * 1024));
                asm volatile("ld.shared.v4.f32 {%0,%1,%2,%3}, [%4];"
                             : "=f"(a4), "=f"(a5), "=f"(a6), "=f"(a7)
                             : "r"(wb + k * 1024 + 16));
                unsigned long long xp0, xp1, xp2, xp3;
                asm volatile("ld.shared.v2.b64 {%0,%1}, [%2];"
                             : "=l"(xp0), "=l"(xp1) : "r"(xb1 + k * 512));
                asm volatile("ld.shared.v2.b64 {%0,%1}, [%2];"
                             : "=l"(xp2), "=l"(xp3) : "r"(xb1 + k * 512 + 16));
                unsigned long long wd[8];
                wd[0] = pack2(a0, a0); wd[1] = pack2(a1, a1);
                wd[2] = pack2(a2, a2); wd[3] = pack2(a3, a3);
                wd[4] = pack2(a4, a4); wd[5] = pack2(a5, a5);
                wd[6] = pack2(a6, a6); wd[7] = pack2(a7, a7);
#pragma unroll
                for (int m = 0; m < 8; m++) {
                    FMA2(acc1[m * 4 + 0], xp0, wd[m], acc1[m * 4 + 0]);
                    FMA2(acc1[m * 4 + 1], xp1, wd[m], acc1[m * 4 + 1]);
                    FMA2(acc1[m * 4 + 2], xp2, wd[m], acc1[m * 4 + 2]);
                    FMA2(acc1[m * 4 + 3], xp3, wd[m], acc1[m * 4 + 3]);
                }
            }

            // ---- bias + exact GELU -> hs[jloc][p]
#pragma unroll
            for (int m = 0; m < 8; m++) {
                const int jloc = (g1 << 3) + m;
                const float bj = b1s[(half << 7) + jloc];
#pragma unroll
                for (int q = 0; q < 4; q++) {
                    float lo, hi;
                    unpack2(acc1[m * 4 + q], lo, hi);
                    lo = gelu_exact(lo + bj);
                    hi = gelu_exact(hi + bj);
                    asm volatile("st.shared.b64 [%0], %1;" ::
                                 "r"(s_h + (unsigned)(((jloc << 7) + (g2 << 3) + (q << 1)) << 2)),
                                 "l"(pack2(lo, hi)));
                }
            }
            __syncthreads();

            // ---- GEMM2: accumulate k in [half*128, half*128+128)
            const unsigned w2b = s_w2 + (unsigned)((((half << 7) << 6) + (g1 << 2)) << 2);
            const unsigned hb  = s_h + (unsigned)((g2 << 3) << 2);
#pragma unroll 4
            for (int kk = 0; kk < 128; kk++) {
                float c0, c1, c2, c3;
                asm volatile("ld.shared.v4.f32 {%0,%1,%2,%3}, [%4];"
                             : "=f"(c0), "=f"(c1), "=f"(c2), "=f"(c3)
                             : "r"(w2b + kk * 256));
                unsigned long long hp0, hp1, hp2, hp3;
                asm volatile("ld.shared.v2.b64 {%0,%1}, [%2];"
                             : "=l"(hp0), "=l"(hp1) : "r"(hb + kk * 512));
                asm volatile("ld.shared.v2.b64 {%0,%1}, [%2];"
                             : "=l"(hp2), "=l"(hp3) : "r"(hb + kk * 512 + 16));
                unsigned long long cd0 = pack2(c0, c0), cd1 = pack2(c1, c1);
                unsigned long long cd2 = pack2(c2, c2), cd3 = pack2(c3, c3);
                FMA2(acc2[0],  hp0, cd0, acc2[0]);
                FMA2(acc2[1],  hp1, cd0, acc2[1]);
                FMA2(acc2[2],  hp2, cd0, acc2[2]);
                FMA2(acc2[3],  hp3, cd0, acc2[3]);
                FMA2(acc2[4],  hp0, cd1, acc2[4]);
                FMA2(acc2[5],  hp1, cd1, acc2[5]);
                FMA2(acc2[6],  hp2, cd1, acc2[6]);
                FMA2(acc2[7],  hp3, cd1, acc2[7]);
                FMA2(acc2[8],  hp0, cd2, acc2[8]);
                FMA2(acc2[9],  hp1, cd2, acc2[9]);
                FMA2(acc2[10], hp2, cd2, acc2[10]);
                FMA2(acc2[11], hp3, cd2, acc2[11]);
                FMA2(acc2[12], hp0, cd3, acc2[12]);
                FMA2(acc2[13], hp1, cd3, acc2[13]);
                FMA2(acc2[14], hp2, cd3, acc2[14]);
                FMA2(acc2[15], hp3, cd3, acc2[15]);
            }
        } // half

        // ---- epilogue: bias2, write y tile (coalesced float4)
        float* yb = g_y + (b << 22) + pixbase + (g2 << 3);
#pragma unroll
        for (int m = 0; m < 4; m++) {
            const int c = (g1 << 2) + m;
            const float bc = b2s[c];
            float o0, o1, o2, o3, o4, o5, o6, o7;
            unpack2(acc2[m * 4 + 0], o0, o1);
            unpack2(acc2[m * 4 + 1], o2, o3);
            unpack2(acc2[m * 4 + 2], o4, o5);
            unpack2(acc2[m * 4 + 3], o6, o7);
            float* yc = yb + (c << 16);
            *reinterpret_cast<float4*>(yc)     = make_float4(o0 + bc, o1 + bc, o2 + bc, o3 + bc);
            *reinterpret_cast<float4*>(yc + 4) = make_float4(o4 + bc, o5 + bc, o6 + bc, o7 + bc);
        }
    }
}

// ---------------------------------------------------------------------------
// Kernel 3: per-window 4x4 circular convolution with K_c.
// (unchanged — verified correct, near memory roofline)
// ---------------------------------------------------------------------------
__global__ void __launch_bounds__(256)
winconv_kernel(float* __restrict__ out) {
    const int idx = blockIdx.x * 256 + threadIdx.x;   // window id
    const int wx = idx & 63;
    const int wy = (idx >> 6) & 63;
    const int c  = (idx >> 12) & 63;
    const int b  = idx >> 18;

    __shared__ float Ks[16];
    if (threadIdx.x < 16) Ks[threadIdx.x] = g_K[(c << 4) + threadIdx.x];  // c uniform per block
    __syncthreads();

    float kr[16];
#pragma unroll
    for (int i = 0; i < 16; i++) kr[i] = Ks[i];

    const int base = (((b << 6) + c) << 16) + (wy << 2) * W_ + (wx << 2);
    const float* yp = g_y + base;

    float4 r0 = *reinterpret_cast<const float4*>(yp);
    float4 r1 = *reinterpret_cast<const float4*>(yp + W_);
    float4 r2 = *reinterpret_cast<const float4*>(yp + 2 * W_);
    float4 r3 = *reinterpret_cast<const float4*>(yp + 3 * W_);
    const float vv[16] = {r0.x, r0.y, r0.z, r0.w,
                          r1.x, r1.y, r1.z, r1.w,
                          r2.x, r2.y, r2.z, r2.w,
                          r3.x, r3.y, r3.z, r3.w};

#pragma unroll
    for (int ro = 0; ro < 4; ro++) {
        float o0 = 0.f, o1 = 0.f, o2 = 0.f, o3 = 0.f;
#pragma unroll
        for (int r = 0; r < 4; r++) {
            const int dp4 = ((ro - r) & 3) * 4;
#pragma unroll
            for (int s = 0; s < 4; s++) {
                const float v = vv[r * 4 + s];
                o0 = fmaf(kr[dp4 + ((0 - s) & 3)], v, o0);
                o1 = fmaf(kr[dp4 + ((1 - s) & 3)], v, o1);
                o2 = fmaf(kr[dp4 + ((2 - s) & 3)], v, o2);
                o3 = fmaf(kr[dp4 + ((3 - s) & 3)], v, o3);
            }
        }
        *reinterpret_cast<float4*>(out + base + ro * W_) = make_float4(o0, o1, o2, o3);
    }
}

// ---------------------------------------------------------------------------
extern "C" void kernel_launch(void* const* d_in, const int* in_sizes, int n_in,
                              void* d_out, int out_size) {
    const float* x  = (const float*)d_in[0];
    const float* w1 = (const float*)d_in[1];
    const float* b1 = (const float*)d_in[2];
    const float* w2 = (const float*)d_in[3];
    const float* b2 = (const float*)d_in[4];
    const float* cw = (const float*)d_in[5];
    float* out = (float*)d_out;

    const int smem_bytes = 57664 * (int)sizeof(float);   // 230656 B (<= 227KB optin)
    cudaFuncSetAttribute(ffn_kernel, cudaFuncAttributeMaxDynamicSharedMemorySize, smem_bytes);

    prep_K_kernel<<<1, 64>>>(cw);
    ffn_kernel<<<148, 256, smem_bytes>>>(x, w1, b1, w2, b2);
    winconv_kernel<<<(B_ * C_ * (H_ / P_) * (W_ / P_)) / 256, 256>>>(out);
}

// round 8
// speedup vs baseline: 1.9527x; 1.5388x over previous
#include <cuda_runtime.h>
#include <cuda_bf16.h>
#include <math.h>
#include <stdint.h>

// Shapes (fixed by the problem)
#define B_  8
#define C_  64
#define HID_ 256
#define H_  256
#define W_  256
#define HW_ (H_*W_)          // 65536
#define P_  4

#define TILE_PIX 128
#define NTILES   (B_*HW_/TILE_PIX)   // 4096

// Scratch
__device__ float g_y[B_ * C_ * HW_];      // 134 MB
__device__ float g_K[C_ * 16];            // 4 KB

// ---------------------------------------------------------------------------
// Kernel 1: per-channel 4x4 circular-conv kernel from cweight (unchanged).
// ---------------------------------------------------------------------------
__global__ void prep_K_kernel(const float* __restrict__ cw) {
    int c = threadIdx.x;
    if (c >= C_) return;
    float Wr[4][4], Wi[4][4];
#pragma unroll
    for (int u = 0; u < 4; u++) {
#pragma unroll
        for (int v = 0; v < 3; v++) {
            int o = ((u * 3 + v) * C_ + c) * 2;
            Wr[u][v] = cw[o];
            Wi[u][v] = cw[o + 1];
        }
        int mu = (4 - u) & 3;
        int o = ((mu * 3 + 1) * C_ + c) * 2;
        Wr[u][3] = cw[o];
        Wi[u][3] = -cw[o + 1];
    }
    const float ct[4] = {1.f, 0.f, -1.f, 0.f};
    const float st[4] = {0.f, 1.f, 0.f, -1.f};
#pragma unroll
    for (int dp = 0; dp < 4; dp++)
#pragma unroll
        for (int dq = 0; dq < 4; dq++) {
            float s = 0.f;
#pragma unroll
            for (int u = 0; u < 4; u++)
#pragma unroll
                for (int v = 0; v < 4; v++) {
                    int m = (u * dp + v * dq) & 3;
                    s += Wr[u][v] * ct[m] - Wi[u][v] * st[m];
                }
            g_K[c * 16 + dp * 4 + dq] = s * (1.f / 16.f);
        }
}

// ---------------------------------------------------------------------------
// Warp-MMA helpers (sm_80-class PTX: valid on plain sm_103 target)
// ---------------------------------------------------------------------------
__device__ __forceinline__ uint32_t smem_u32(const void* p) {
    uint32_t a;
    asm("{ .reg .u64 t; cvta.to.shared.u64 t, %1; cvt.u32.u64 %0, t; }" : "=r"(a) : "l"(p));
    return a;
}
__device__ __forceinline__ void ldmx4(uint32_t* r, uint32_t addr) {
    asm volatile("ldmatrix.sync.aligned.m8n8.x4.shared.b16 {%0,%1,%2,%3}, [%4];"
        : "=r"(r[0]), "=r"(r[1]), "=r"(r[2]), "=r"(r[3]) : "r"(addr));
}
__device__ __forceinline__ void mma_bf16(float* d, const uint32_t* a, const uint32_t* b) {
    asm volatile("mma.sync.aligned.m16n8k16.row.col.f32.bf16.bf16.f32 "
        "{%0,%1,%2,%3}, {%4,%5,%6,%7}, {%8,%9}, {%0,%1,%2,%3};"
        : "+f"(d[0]), "+f"(d[1]), "+f"(d[2]), "+f"(d[3])
        : "r"(a[0]), "r"(a[1]), "r"(a[2]), "r"(a[3]), "r"(b[0]), "r"(b[1]));
}

// XOR-swizzled byte offset inside a row-major smem tile.
// Swizzle permutes 16B chunks by (row & 7) -> conflict-free ldmatrix + STS.
__device__ __forceinline__ uint32_t swoff(uint32_t region, int row, int byte_col, int stride) {
    uint32_t b = (uint32_t)byte_col;
    return region + (uint32_t)(row * stride) + (b & 15u) + ((((b >> 4) ^ (uint32_t)(row & 7))) << 4);
}

__device__ __forceinline__ float gelu_exact(float h) {
    return 0.5f * h * (1.0f + erff(h * 0.70710678118654752f));
}
__device__ __forceinline__ void split_bf16(float v, uint16_t& hi, uint16_t& lo) {
    __nv_bfloat16 h = __float2bfloat16_rn(v);
    float r = v - __bfloat162float(h);
    __nv_bfloat16 l = __float2bfloat16_rn(r);
    hi = *reinterpret_cast<uint16_t*>(&h);
    lo = *reinterpret_cast<uint16_t*>(&l);
}
__device__ __forceinline__ uint32_t pack_bf2(uint16_t e0, uint16_t e1) {
    return (uint32_t)e0 | ((uint32_t)e1 << 16);
}

// smem regions (bytes). All tiles row-major bf16 with XOR swizzle.
#define R_XHI   0u         // X  [128p][64k]   stride 128B, 16 KB
#define R_XLO   16384u
#define R_W1HI  32768u     // W1 [256j][64k]   stride 128B, 32 KB
#define R_W1LO  65536u
#define R_W2HI  98304u     // W2 [64c][256j]   stride 512B, 32 KB
#define R_W2LO  131072u
#define R_HHI   163840u    // H  [128p][128j]  stride 256B, 32 KB (per half)
#define R_HLO   196608u
#define R_B1    229376u    // 256 floats
#define R_B2    230400u    // 64 floats
#define SMEM_FFN 230656u

// ---------------------------------------------------------------------------
// Kernel 2: FFN via bf16x3-split mma.sync GEMMs. Persistent, grid=148, 256 thr.
// GEMM1: D1[p,j] = X[p,k] W1[j,k]^T (K=64), two j-halves of 128
// GEMM2: D2[p,c] = H[p,j] W2[c,j]^T (K=256, accumulated across halves)
// Warp layout: wm = (wid&3)*32 pixel rows, wn = wid>>2 column group.
// ---------------------------------------------------------------------------
__global__ void __launch_bounds__(256, 1)
ffn_mma_kernel(const float* __restrict__ x,
               const float* __restrict__ w1,
               const float* __restrict__ b1,
               const float* __restrict__ w2,
               const float* __restrict__ b2) {
    extern __shared__ char smc[];
    const uint32_t sb = smem_u32(smc);
    const int tid = threadIdx.x;
    const int lane = tid & 31;
    const int wid = tid >> 5;
    const int wm = (wid & 3) * 32;
    const int wn = wid >> 2;

    // ---- one-time: weights -> split bf16, swizzled smem ----
    {   // W1: thread = row j
        const int j = tid;
        const float* wr = w1 + j * 64;
#pragma unroll
        for (int g = 0; g < 8; g++) {
            uint16_t hi[8], lo[8];
#pragma unroll
            for (int e = 0; e < 8; e++) split_bf16(wr[g * 8 + e], hi[e], lo[e]);
            uint32_t off = swoff(R_W1HI, j, g * 16, 128);
            *reinterpret_cast<uint4*>(smc + off) = *reinterpret_cast<uint4*>(hi);
            *reinterpret_cast<uint4*>(smc + off + (R_W1LO - R_W1HI)) = *reinterpret_cast<uint4*>(lo);
        }
    }
    {   // W2: thread = (c row, j quarter)
        const int c = tid >> 2, jg = tid & 3;
        const float* wr = w2 + c * 256 + jg * 64;
#pragma unroll
        for (int g = 0; g < 8; g++) {
            uint16_t hi[8], lo[8];
#pragma unroll
            for (int e = 0; e < 8; e++) split_bf16(wr[g * 8 + e], hi[e], lo[e]);
            uint32_t off = swoff(R_W2HI, c, jg * 128 + g * 16, 512);
            *reinterpret_cast<uint4*>(smc + off) = *reinterpret_cast<uint4*>(hi);
            *reinterpret_cast<uint4*>(smc + off + (R_W2LO - R_W2HI)) = *reinterpret_cast<uint4*>(lo);
        }
    }
    *reinterpret_cast<float*>(smc + R_B1 + tid * 4) = b1[tid];
    if (tid < 64) *reinterpret_cast<float*>(smc + R_B2 + tid * 4) = b2[tid];

    const float* b1s = reinterpret_cast<const float*>(smc + R_B1);
    const float* b2s = reinterpret_cast<const float*>(smc + R_B2);

    // ldmatrix per-lane address components (constant per thread)
    const int a_r = lane & 15;                 // A-frag row within m16
    const int a_b = (lane >> 4) << 4;          // A-frag k-byte (+16 for k8-15)
    const int b_r = (lane & 7) + ((lane >> 4) << 3);   // B-frag n row within n16
    const int b_b = ((lane >> 3) & 1) << 4;            // B-frag k-byte
    const int prow = lane >> 2;                // D-frag row
    const int jcol = (lane & 3) * 2;           // D-frag col

    for (int tile = blockIdx.x; tile < NTILES; tile += gridDim.x) {
        const int b = tile >> 9;
        const int pixbase = (tile & 511) << 7;

        // ---- stage X: load, split, store swizzled bf16 ----
        {
            const int ch = tid >> 2, pg = tid & 3;
            const float* xp = x + ((size_t)b << 22) + ((size_t)ch << 16) + pixbase + pg * 32;
#pragma unroll
            for (int i = 0; i < 32; i++) {
                uint16_t hi, lo;
                split_bf16(xp[i], hi, lo);
                uint32_t off = swoff(R_XHI, pg * 32 + i, ch * 2, 128);
                *reinterpret_cast<uint16_t*>(smc + off) = hi;
                *reinterpret_cast<uint16_t*>(smc + off + (R_XLO - R_XHI)) = lo;
            }
        }
        __syncthreads();

        float acc2[2][4][4];
#pragma unroll
        for (int mt = 0; mt < 2; mt++)
#pragma unroll
            for (int nt = 0; nt < 4; nt++)
#pragma unroll
                for (int q = 0; q < 4; q++) acc2[mt][nt][q] = 0.f;

#pragma unroll 1
        for (int half = 0; half < 2; half++) {
            // ======== GEMM1: 32p x 64j per warp, K=64 ========
            float acc1[2][8][4];
#pragma unroll
            for (int mt = 0; mt < 2; mt++)
#pragma unroll
                for (int nt = 0; nt < 8; nt++)
#pragma unroll
                    for (int q = 0; q < 4; q++) acc1[mt][nt][q] = 0.f;

#pragma unroll 1
            for (int kt = 0; kt < 4; kt++) {
                uint32_t ah0[4], ah1[4], al0[4], al1[4];
                ldmx4(ah0, sb + swoff(R_XHI, wm + a_r,      kt * 32 + a_b, 128));
                ldmx4(ah1, sb + swoff(R_XHI, wm + 16 + a_r, kt * 32 + a_b, 128));
                ldmx4(al0, sb + swoff(R_XLO, wm + a_r,      kt * 32 + a_b, 128));
                ldmx4(al1, sb + swoff(R_XLO, wm + 16 + a_r, kt * 32 + a_b, 128));
#pragma unroll
                for (int g = 0; g < 4; g++) {
                    const int n0 = half * 128 + wn * 64 + g * 16;
                    uint32_t bh[4], bl[4];
                    ldmx4(bh, sb + swoff(R_W1HI, n0 + b_r, kt * 32 + b_b, 128));
                    ldmx4(bl, sb + swoff(R_W1LO, n0 + b_r, kt * 32 + b_b, 128));
                    mma_bf16(acc1[0][2 * g],     ah0, bh);
                    mma_bf16(acc1[0][2 * g],     ah0, bl);
                    mma_bf16(acc1[0][2 * g],     al0, bh);
                    mma_bf16(acc1[0][2 * g + 1], ah0, bh + 2);
                    mma_bf16(acc1[0][2 * g + 1], ah0, bl + 2);
                    mma_bf16(acc1[0][2 * g + 1], al0, bh + 2);
                    mma_bf16(acc1[1][2 * g],     ah1, bh);
                    mma_bf16(acc1[1][2 * g],     ah1, bl);
                    mma_bf16(acc1[1][2 * g],     al1, bh);
                    mma_bf16(acc1[1][2 * g + 1], ah1, bh + 2);
                    mma_bf16(acc1[1][2 * g + 1], ah1, bl + 2);
                    mma_bf16(acc1[1][2 * g + 1], al1, bh + 2);
                }
            }

            // ======== bias + GELU -> split -> H smem ========
#pragma unroll
            for (int mt = 0; mt < 2; mt++)
#pragma unroll
                for (int nt = 0; nt < 8; nt++) {
                    const int p = wm + mt * 16 + prow;
                    const int j = wn * 64 + nt * 8 + jcol;
                    const float bj0 = b1s[half * 128 + j];
                    const float bj1 = b1s[half * 128 + j + 1];
                    float v0 = gelu_exact(acc1[mt][nt][0] + bj0);
                    float v1 = gelu_exact(acc1[mt][nt][1] + bj1);
                    float v2 = gelu_exact(acc1[mt][nt][2] + bj0);
                    float v3 = gelu_exact(acc1[mt][nt][3] + bj1);
                    uint16_t h0, l0, h1, l1, h2, l2, h3, l3;
                    split_bf16(v0, h0, l0); split_bf16(v1, h1, l1);
                    split_bf16(v2, h2, l2); split_bf16(v3, h3, l3);
                    uint32_t o0 = swoff(R_HHI, p, j * 2, 256);
                    uint32_t o1 = swoff(R_HHI, p + 8, j * 2, 256);
                    *reinterpret_cast<uint32_t*>(smc + o0) = pack_bf2(h0, h1);
                    *reinterpret_cast<uint32_t*>(smc + o1) = pack_bf2(h2, h3);
                    *reinterpret_cast<uint32_t*>(smc + o0 + (R_HLO - R_HHI)) = pack_bf2(l0, l1);
                    *reinterpret_cast<uint32_t*>(smc + o1 + (R_HLO - R_HHI)) = pack_bf2(l2, l3);
                }
            __syncthreads();

            // ======== GEMM2: 32p x 32c per warp, K=128 this half ========
#pragma unroll 1
            for (int kt = 0; kt < 8; kt++) {
                uint32_t ah0[4], ah1[4], al0[4], al1[4];
                ldmx4(ah0, sb + swoff(R_HHI, wm + a_r,      kt * 32 + a_b, 256));
                ldmx4(ah1, sb + swoff(R_HHI, wm + 16 + a_r, kt * 32 + a_b, 256));
                ldmx4(al0, sb + swoff(R_HLO, wm + a_r,      kt * 32 + a_b, 256));
                ldmx4(al1, sb + swoff(R_HLO, wm + 16 + a_r, kt * 32 + a_b, 256));
#pragma unroll
                for (int g = 0; g < 2; g++) {
                    const int n0 = wn * 32 + g * 16;
                    const int kb = half * 256 + kt * 32 + b_b;
                    uint32_t bh[4], bl[4];
                    ldmx4(bh, sb + swoff(R_W2HI, n0 + b_r, kb, 512));
                    ldmx4(bl, sb + swoff(R_W2LO, n0 + b_r, kb, 512));
                    mma_bf16(acc2[0][2 * g],     ah0, bh);
                    mma_bf16(acc2[0][2 * g],     ah0, bl);
                    mma_bf16(acc2[0][2 * g],     al0, bh);
                    mma_bf16(acc2[0][2 * g + 1], ah0, bh + 2);
                    mma_bf16(acc2[0][2 * g + 1], ah0, bl + 2);
                    mma_bf16(acc2[0][2 * g + 1], al0, bh + 2);
                    mma_bf16(acc2[1][2 * g],     ah1, bh);
                    mma_bf16(acc2[1][2 * g],     ah1, bl);
                    mma_bf16(acc2[1][2 * g],     al1, bh);
                    mma_bf16(acc2[1][2 * g + 1], ah1, bh + 2);
                    mma_bf16(acc2[1][2 * g + 1], ah1, bl + 2);
                    mma_bf16(acc2[1][2 * g + 1], al1, bh + 2);
                }
            }
            __syncthreads();   // all warps done reading H before next overwrite
        }

        // ---- epilogue: +b2, write y ----
        float* yb = g_y + ((size_t)b << 22) + pixbase;
#pragma unroll
        for (int mt = 0; mt < 2; mt++)
#pragma unroll
            for (int nt = 0; nt < 4; nt++) {
                const int p = wm + mt * 16 + prow;
                const int c = wn * 32 + nt * 8 + jcol;
                yb[((size_t)c << 16) + p]           = acc2[mt][nt][0] + b2s[c];
                yb[((size_t)(c + 1) << 16) + p]     = acc2[mt][nt][1] + b2s[c + 1];
                yb[((size_t)c << 16) + p + 8]       = acc2[mt][nt][2] + b2s[c];
                yb[((size_t)(c + 1) << 16) + p + 8] = acc2[mt][nt][3] + b2s[c + 1];
            }
    }
}

// ---------------------------------------------------------------------------
// Kernel 3: per-window 4x4 circular convolution (unchanged).
// ---------------------------------------------------------------------------
__global__ void __launch_bounds__(256)
winconv_kernel(float* __restrict__ out) {
    const int idx = blockIdx.x * 256 + threadIdx.x;
    const int wx = idx & 63;
    const int wy = (idx >> 6) & 63;
    const int c  = (idx >> 12) & 63;
    const int b  = idx >> 18;

    __shared__ float Ks[16];
    if (threadIdx.x < 16) Ks[threadIdx.x] = g_K[(c << 4) + threadIdx.x];
    __syncthreads();

    float kr[16];
#pragma unroll
    for (int i = 0; i < 16; i++) kr[i] = Ks[i];

    const int base = (((b << 6) + c) << 16) + (wy << 2) * W_ + (wx << 2);
    const float* yp = g_y + base;

    float4 r0 = *reinterpret_cast<const float4*>(yp);
    float4 r1 = *reinterpret_cast<const float4*>(yp + W_);
    float4 r2 = *reinterpret_cast<const float4*>(yp + 2 * W_);
    float4 r3 = *reinterpret_cast<const float4*>(yp + 3 * W_);
    const float vv[16] = {r0.x, r0.y, r0.z, r0.w,
                          r1.x, r1.y, r1.z, r1.w,
                          r2.x, r2.y, r2.z, r2.w,
                          r3.x, r3.y, r3.z, r3.w};

#pragma unroll
    for (int ro = 0; ro < 4; ro++) {
        float o0 = 0.f, o1 = 0.f, o2 = 0.f, o3 = 0.f;
#pragma unroll
        for (int r = 0; r < 4; r++) {
            const int dp4 = ((ro - r) & 3) * 4;
#pragma unroll
            for (int s = 0; s < 4; s++) {
                const float v = vv[r * 4 + s];
                o0 = fmaf(kr[dp4 + ((0 - s) & 3)], v, o0);
                o1 = fmaf(kr[dp4 + ((1 - s) & 3)], v, o1);
                o2 = fmaf(kr[dp4 + ((2 - s) & 3)], v, o2);
                o3 = fmaf(kr[dp4 + ((3 - s) & 3)], v, o3);
            }
        }
        *reinterpret_cast<float4*>(out + base + ro * W_) = make_float4(o0, o1, o2, o3);
    }
}

// ---------------------------------------------------------------------------
extern "C" void kernel_launch(void* const* d_in, const int* in_sizes, int n_in,
                              void* d_out, int out_size) {
    const float* x  = (const float*)d_in[0];
    const float* w1 = (const float*)d_in[1];
    const float* b1 = (const float*)d_in[2];
    const float* w2 = (const float*)d_in[3];
    const float* b2 = (const float*)d_in[4];
    const float* cw = (const float*)d_in[5];
    float* out = (float*)d_out;

    cudaFuncSetAttribute(ffn_mma_kernel, cudaFuncAttributeMaxDynamicSharedMemorySize, SMEM_FFN);

    prep_K_kernel<<<1, 64>>>(cw);
    ffn_mma_kernel<<<148, 256, SMEM_FFN>>>(x, w1, b1, w2, b2);
    winconv_kernel<<<(B_ * C_ * (H_ / P_) * (W_ / P_)) / 256, 256>>>(out);
}

// round 9
// speedup vs baseline: 3.0138x; 1.5434x over previous
#include <cuda_runtime.h>
#include <cuda_bf16.h>
#include <cuda_fp16.h>
#include <math.h>
#include <stdint.h>

// Shapes (fixed by the problem)
#define B_  8
#define C_  64
#define HID_ 256
#define H_  256
#define W_  256
#define HW_ (H_*W_)          // 65536
#define P_  4

#define TILE_PIX 128
#define NTILES   (B_*HW_/TILE_PIX)   // 4096

// Scratch
__device__ float g_y[B_ * C_ * HW_];      // 134 MB
__device__ float g_K[C_ * 16];            // 4 KB

// ---------------------------------------------------------------------------
// Kernel 1: per-channel 4x4 circular-conv kernel from cweight (unchanged).
// ---------------------------------------------------------------------------
__global__ void prep_K_kernel(const float* __restrict__ cw) {
    int c = threadIdx.x;
    if (c >= C_) return;
    float Wr[4][4], Wi[4][4];
#pragma unroll
    for (int u = 0; u < 4; u++) {
#pragma unroll
        for (int v = 0; v < 3; v++) {
            int o = ((u * 3 + v) * C_ + c) * 2;
            Wr[u][v] = cw[o];
            Wi[u][v] = cw[o + 1];
        }
        int mu = (4 - u) & 3;
        int o = ((mu * 3 + 1) * C_ + c) * 2;
        Wr[u][3] = cw[o];
        Wi[u][3] = -cw[o + 1];
    }
    const float ct[4] = {1.f, 0.f, -1.f, 0.f};
    const float st[4] = {0.f, 1.f, 0.f, -1.f};
#pragma unroll
    for (int dp = 0; dp < 4; dp++)
#pragma unroll
        for (int dq = 0; dq < 4; dq++) {
            float s = 0.f;
#pragma unroll
            for (int u = 0; u < 4; u++)
#pragma unroll
                for (int v = 0; v < 4; v++) {
                    int m = (u * dp + v * dq) & 3;
                    s += Wr[u][v] * ct[m] - Wi[u][v] * st[m];
                }
            g_K[c * 16 + dp * 4 + dq] = s * (1.f / 16.f);
        }
}

// ---------------------------------------------------------------------------
// Warp-MMA helpers (sm_80-class PTX: valid on plain sm_103 target)
// ---------------------------------------------------------------------------
__device__ __forceinline__ uint32_t smem_u32(const void* p) {
    uint32_t a;
    asm("{ .reg .u64 t; cvta.to.shared.u64 t, %1; cvt.u32.u64 %0, t; }" : "=r"(a) : "l"(p));
    return a;
}
__device__ __forceinline__ void ldmx4(uint32_t* r, uint32_t addr) {
    asm volatile("ldmatrix.sync.aligned.m8n8.x4.shared.b16 {%0,%1,%2,%3}, [%4];"
        : "=r"(r[0]), "=r"(r[1]), "=r"(r[2]), "=r"(r[3]) : "r"(addr));
}
__device__ __forceinline__ void mma_f16(float* d, const uint32_t* a, const uint32_t* b) {
    asm volatile("mma.sync.aligned.m16n8k16.row.col.f32.f16.f16.f32 "
        "{%0,%1,%2,%3}, {%4,%5,%6,%7}, {%8,%9}, {%0,%1,%2,%3};"
        : "+f"(d[0]), "+f"(d[1]), "+f"(d[2]), "+f"(d[3])
        : "r"(a[0]), "r"(a[1]), "r"(a[2]), "r"(a[3]), "r"(b[0]), "r"(b[1]));
}

// XOR-swizzled byte offset inside a row-major smem tile (16B chunk permute).
__device__ __forceinline__ uint32_t swoff(uint32_t region, int row, int byte_col, int stride) {
    uint32_t b = (uint32_t)byte_col;
    return region + (uint32_t)(row * stride) + (b & 15u) + ((((b >> 4) ^ (uint32_t)(row & 7))) << 4);
}

__device__ __forceinline__ float gelu_exact(float h) {
    return 0.5f * h * (1.0f + erff(h * 0.70710678118654752f));
}
// Split fp32 into fp16 hi + fp16 residual (weights only; one-time).
__device__ __forceinline__ void split_f16(float v, uint16_t& hi, uint16_t& lo) {
    __half h = __float2half_rn(v);
    float r = v - __half2float(h);
    __half l = __float2half_rn(r);
    hi = __half_as_ushort(h);
    lo = __half_as_ushort(l);
}
__device__ __forceinline__ uint32_t pack_h2(uint16_t e0, uint16_t e1) {
    return (uint32_t)e0 | ((uint32_t)e1 << 16);
}

// smem regions (bytes). Row-major fp16 tiles with XOR swizzle.
#define R_X     0u         // X  [128p][64k]   stride 128B, 16 KB (single fp16)
#define R_W1HI  16384u     // W1 [256j][64k]   stride 128B, 16 KB each
#define R_W1LO  49152u     //   (hi at 16384, lo at 49152; note hi is 32KB region? no: 256*128B = 32 KB)
#define R_W2HI  81920u     // W2 [64c][256j]   stride 512B, 32 KB each
#define R_W2LO  114688u
#define R_H     147456u    // H  [128p][128j]  stride 256B, 32 KB (single fp16)
#define R_B1    180224u    // 256 floats
#define R_B2    181248u    // 64 floats
#define SMEM_FFN 181504u

// ---------------------------------------------------------------------------
// Kernel 2: FFN via fp16 2-product-split mma.sync GEMMs. grid=148, 256 thr.
// GEMM1: D1[p,j] = X[p,k] (W1hi+W1lo)[j,k]^T (K=64), two j-halves of 128
// GEMM2: D2[p,c] = H[p,j] (W2hi+W2lo)[c,j]^T (K=256, accumulated over halves)
// Dropped terms: x_residual*W1, h_residual*W2  (~2.4e-4 rel each).
// ---------------------------------------------------------------------------
__global__ void __launch_bounds__(256, 1)
ffn_mma_kernel(const float* __restrict__ x,
               const float* __restrict__ w1,
               const float* __restrict__ b1,
               const float* __restrict__ w2,
               const float* __restrict__ b2) {
    extern __shared__ char smc[];
    const uint32_t sb = smem_u32(smc);
    const int tid = threadIdx.x;
    const int lane = tid & 31;
    const int wid = tid >> 5;
    const int wm = (wid & 3) * 32;
    const int wn = wid >> 2;

    // ---- one-time: weights -> split fp16 hi/lo, swizzled smem ----
    {   // W1: thread = row j (256 rows x 64 k)
        const int j = tid;
        const float* wr = w1 + j * 64;
#pragma unroll
        for (int g = 0; g < 8; g++) {
            uint16_t hi[8], lo[8];
#pragma unroll
            for (int e = 0; e < 8; e++) split_f16(wr[g * 8 + e], hi[e], lo[e]);
            uint32_t off = swoff(R_W1HI, j, g * 16, 128);
            *reinterpret_cast<uint4*>(smc + off) = *reinterpret_cast<uint4*>(hi);
            *reinterpret_cast<uint4*>(smc + off + (R_W1LO - R_W1HI)) = *reinterpret_cast<uint4*>(lo);
        }
    }
    {   // W2: thread = (c row, j quarter)  (64 rows x 256 j)
        const int c = tid >> 2, jg = tid & 3;
        const float* wr = w2 + c * 256 + jg * 64;
#pragma unroll
        for (int g = 0; g < 8; g++) {
            uint16_t hi[8], lo[8];
#pragma unroll
            for (int e = 0; e < 8; e++) split_f16(wr[g * 8 + e], hi[e], lo[e]);
            uint32_t off = swoff(R_W2HI, c, jg * 128 + g * 16, 512);
            *reinterpret_cast<uint4*>(smc + off) = *reinterpret_cast<uint4*>(hi);
            *reinterpret_cast<uint4*>(smc + off + (R_W2LO - R_W2HI)) = *reinterpret_cast<uint4*>(lo);
        }
    }
    *reinterpret_cast<float*>(smc + R_B1 + tid * 4) = b1[tid];
    if (tid < 64) *reinterpret_cast<float*>(smc + R_B2 + tid * 4) = b2[tid];

    const float* b1s = reinterpret_cast<const float*>(smc + R_B1);
    const float* b2s = reinterpret_cast<const float*>(smc + R_B2);

    // ldmatrix per-lane address components (constant per thread)
    const int a_r = lane & 15;
    const int a_b = (lane >> 4) << 4;
    const int b_r = (lane & 7) + ((lane >> 4) << 3);
    const int b_b = ((lane >> 3) & 1) << 4;
    const int prow = lane >> 2;
    const int jcol = (lane & 3) * 2;

    for (int tile = blockIdx.x; tile < NTILES; tile += gridDim.x) {
        const int b = tile >> 9;
        const int pixbase = (tile & 511) << 7;

        // ---- stage X: float4 loads, fp16 round (no split), swizzled store ----
        {
            const int ch = tid >> 2, q = tid & 3;
            const float* xp = x + ((size_t)b << 22) + ((size_t)ch << 16) + pixbase + q * 32;
#pragma unroll
            for (int i4 = 0; i4 < 8; i4++) {
                float4 v = reinterpret_cast<const float4*>(xp)[i4];
                const int r0 = q * 32 + i4 * 4;
                *reinterpret_cast<uint16_t*>(smc + swoff(R_X, r0,     ch * 2, 128)) = __half_as_ushort(__float2half_rn(v.x));
                *reinterpret_cast<uint16_t*>(smc + swoff(R_X, r0 + 1, ch * 2, 128)) = __half_as_ushort(__float2half_rn(v.y));
                *reinterpret_cast<uint16_t*>(smc + swoff(R_X, r0 + 2, ch * 2, 128)) = __half_as_ushort(__float2half_rn(v.z));
                *reinterpret_cast<uint16_t*>(smc + swoff(R_X, r0 + 3, ch * 2, 128)) = __half_as_ushort(__float2half_rn(v.w));
            }
        }
        __syncthreads();

        float acc2[2][4][4];
#pragma unroll
        for (int mt = 0; mt < 2; mt++)
#pragma unroll
            for (int nt = 0; nt < 4; nt++)
#pragma unroll
                for (int q = 0; q < 4; q++) acc2[mt][nt][q] = 0.f;

#pragma unroll 1
        for (int half = 0; half < 2; half++) {
            // ======== GEMM1: 32p x 64j per warp, K=64 ========
            float acc1[2][8][4];
#pragma unroll
            for (int mt = 0; mt < 2; mt++)
#pragma unroll
                for (int nt = 0; nt < 8; nt++)
#pragma unroll
                    for (int q = 0; q < 4; q++) acc1[mt][nt][q] = 0.f;

#pragma unroll 1
            for (int kt = 0; kt < 4; kt++) {
                uint32_t a0[4], a1[4];
                ldmx4(a0, sb + swoff(R_X, wm + a_r,      kt * 32 + a_b, 128));
                ldmx4(a1, sb + swoff(R_X, wm + 16 + a_r, kt * 32 + a_b, 128));
#pragma unroll
                for (int g = 0; g < 4; g++) {
                    const int n0 = half * 128 + wn * 64 + g * 16;
                    uint32_t bh[4], bl[4];
                    ldmx4(bh, sb + swoff(R_W1HI, n0 + b_r, kt * 32 + b_b, 128));
                    ldmx4(bl, sb + swoff(R_W1LO, n0 + b_r, kt * 32 + b_b, 128));
                    mma_f16(acc1[0][2 * g],     a0, bh);
                    mma_f16(acc1[0][2 * g],     a0, bl);
                    mma_f16(acc1[0][2 * g + 1], a0, bh + 2);
                    mma_f16(acc1[0][2 * g + 1], a0, bl + 2);
                    mma_f16(acc1[1][2 * g],     a1, bh);
                    mma_f16(acc1[1][2 * g],     a1, bl);
                    mma_f16(acc1[1][2 * g + 1], a1, bh + 2);
                    mma_f16(acc1[1][2 * g + 1], a1, bl + 2);
                }
            }

            // ======== bias + GELU -> fp16 -> H smem ========
#pragma unroll
            for (int mt = 0; mt < 2; mt++)
#pragma unroll
                for (int nt = 0; nt < 8; nt++) {
                    const int p = wm + mt * 16 + prow;
                    const int j = wn * 64 + nt * 8 + jcol;
                    const float bj0 = b1s[half * 128 + j];
                    const float bj1 = b1s[half * 128 + j + 1];
                    float v0 = gelu_exact(acc1[mt][nt][0] + bj0);
                    float v1 = gelu_exact(acc1[mt][nt][1] + bj1);
                    float v2 = gelu_exact(acc1[mt][nt][2] + bj0);
                    float v3 = gelu_exact(acc1[mt][nt][3] + bj1);
                    uint16_t h0 = __half_as_ushort(__float2half_rn(v0));
                    uint16_t h1 = __half_as_ushort(__float2half_rn(v1));
                    uint16_t h2 = __half_as_ushort(__float2half_rn(v2));
                    uint16_t h3 = __half_as_ushort(__float2half_rn(v3));
                    *reinterpret_cast<uint32_t*>(smc + swoff(R_H, p,     j * 2, 256)) = pack_h2(h0, h1);
                    *reinterpret_cast<uint32_t*>(smc + swoff(R_H, p + 8, j * 2, 256)) = pack_h2(h2, h3);
                }
            __syncthreads();

            // ======== GEMM2: 32p x 32c per warp, K=128 this half ========
#pragma unroll 1
            for (int kt = 0; kt < 8; kt++) {
                uint32_t a0[4], a1[4];
                ldmx4(a0, sb + swoff(R_H, wm + a_r,      kt * 32 + a_b, 256));
                ldmx4(a1, sb + swoff(R_H, wm + 16 + a_r, kt * 32 + a_b, 256));
#pragma unroll
                for (int g = 0; g < 2; g++) {
                    const int n0 = wn * 32 + g * 16;
                    const int kb = half * 256 + kt * 32 + b_b;
                    uint32_t bh[4], bl[4];
                    ldmx4(bh, sb + swoff(R_W2HI, n0 + b_r, kb, 512));
                    ldmx4(bl, sb + swoff(R_W2LO, n0 + b_r, kb, 512));
                    mma_f16(acc2[0][2 * g],     a0, bh);
                    mma_f16(acc2[0][2 * g],     a0, bl);
                    mma_f16(acc2[0][2 * g + 1], a0, bh + 2);
                    mma_f16(acc2[0][2 * g + 1], a0, bl + 2);
                    mma_f16(acc2[1][2 * g],     a1, bh);
                    mma_f16(acc2[1][2 * g],     a1, bl);
                    mma_f16(acc2[1][2 * g + 1], a1, bh + 2);
                    mma_f16(acc2[1][2 * g + 1], a1, bl + 2);
                }
            }
            __syncthreads();   // all warps done reading H before next overwrite
        }

        // ---- epilogue: +b2, write y ----
        float* yb = g_y + ((size_t)b << 22) + pixbase;
#pragma unroll
        for (int mt = 0; mt < 2; mt++)
#pragma unroll
            for (int nt = 0; nt < 4; nt++) {
                const int p = wm + mt * 16 + prow;
                const int c = wn * 32 + nt * 8 + jcol;
                yb[((size_t)c << 16) + p]           = acc2[mt][nt][0] + b2s[c];
                yb[((size_t)(c + 1) << 16) + p]     = acc2[mt][nt][1] + b2s[c + 1];
                yb[((size_t)c << 16) + p + 8]       = acc2[mt][nt][2] + b2s[c];
                yb[((size_t)(c + 1) << 16) + p + 8] = acc2[mt][nt][3] + b2s[c + 1];
            }
    }
}

// ---------------------------------------------------------------------------
// Kernel 3: per-window 4x4 circular convolution (unchanged).
// ---------------------------------------------------------------------------
__global__ void __launch_bounds__(256)
winconv_kernel(float* __restrict__ out) {
    const int idx = blockIdx.x * 256 + threadIdx.x;
    const int wx = idx & 63;
    const int wy = (idx >> 6) & 63;
    const int c  = (idx >> 12) & 63;
    const int b  = idx >> 18;

    __shared__ float Ks[16];
    if (threadIdx.x < 16) Ks[threadIdx.x] = g_K[(c << 4) + threadIdx.x];
    __syncthreads();

    float kr[16];
#pragma unroll
    for (int i = 0; i < 16; i++) kr[i] = Ks[i];

    const int base = (((b << 6) + c) << 16) + (wy << 2) * W_ + (wx << 2);
    const float* yp = g_y + base;

    float4 r0 = *reinterpret_cast<const float4*>(yp);
    float4 r1 = *reinterpret_cast<const float4*>(yp + W_);
    float4 r2 = *reinterpret_cast<const float4*>(yp + 2 * W_);
    float4 r3 = *reinterpret_cast<const float4*>(yp + 3 * W_);
    const float vv[16] = {r0.x, r0.y, r0.z, r0.w,
                          r1.x, r1.y, r1.z, r1.w,
                          r2.x, r2.y, r2.z, r2.w,
                          r3.x, r3.y, r3.z, r3.w};

#pragma unroll
    for (int ro = 0; ro < 4; ro++) {
        float o0 = 0.f, o1 = 0.f, o2 = 0.f, o3 = 0.f;
#pragma unroll
        for (int r = 0; r < 4; r++) {
            const int dp4 = ((ro - r) & 3) * 4;
#pragma unroll
            for (int s = 0; s < 4; s++) {
                const float v = vv[r * 4 + s];
                o0 = fmaf(kr[dp4 + ((0 - s) & 3)], v, o0);
                o1 = fmaf(kr[dp4 + ((1 - s) & 3)], v, o1);
                o2 = fmaf(kr[dp4 + ((2 - s) & 3)], v, o2);
                o3 = fmaf(kr[dp4 + ((3 - s) & 3)], v, o3);
            }
        }
        *reinterpret_cast<float4*>(out + base + ro * W_) = make_float4(o0, o1, o2, o3);
    }
}

// ---------------------------------------------------------------------------
extern "C" void kernel_launch(void* const* d_in, const int* in_sizes, int n_in,
                              void* d_out, int out_size) {
    const float* x  = (const float*)d_in[0];
    const float* w1 = (const float*)d_in[1];
    const float* b1 = (const float*)d_in[2];
    const float* w2 = (const float*)d_in[3];
    const float* b2 = (const float*)d_in[4];
    const float* cw = (const float*)d_in[5];
    float* out = (float*)d_out;

    cudaFuncSetAttribute(ffn_mma_kernel, cudaFuncAttributeMaxDynamicSharedMemorySize, SMEM_FFN);

    prep_K_kernel<<<1, 64>>>(cw);
    ffn_mma_kernel<<<148, 256, SMEM_FFN>>>(x, w1, b1, w2, b2);
    winconv_kernel<<<(B_ * C_ * (H_ / P_) * (W_ / P_)) / 256, 256>>>(out);
}

// round 10
// speedup vs baseline: 3.4616x; 1.1486x over previous
#include <cuda_runtime.h>
#include <cuda_bf16.h>
#include <cuda_fp16.h>
#include <math.h>
#include <stdint.h>

// Shapes (fixed by the problem)
#define B_  8
#define C_  64
#define HID_ 256
#define H_  256
#define W_  256
#define HW_ (H_*W_)          // 65536
#define P_  4

#define TILE_PIX 128
#define NTILES   (B_*HW_/TILE_PIX)   // 4096

// Scratch
__device__ float g_y[B_ * C_ * HW_];      // 134 MB
__device__ float g_K[C_ * 16];            // 4 KB

// ---------------------------------------------------------------------------
// Kernel 1: per-channel 4x4 circular-conv kernel from cweight (unchanged).
// ---------------------------------------------------------------------------
__global__ void prep_K_kernel(const float* __restrict__ cw) {
    int c = threadIdx.x;
    if (c >= C_) return;
    float Wr[4][4], Wi[4][4];
#pragma unroll
    for (int u = 0; u < 4; u++) {
#pragma unroll
        for (int v = 0; v < 3; v++) {
            int o = ((u * 3 + v) * C_ + c) * 2;
            Wr[u][v] = cw[o];
            Wi[u][v] = cw[o + 1];
        }
        int mu = (4 - u) & 3;
        int o = ((mu * 3 + 1) * C_ + c) * 2;
        Wr[u][3] = cw[o];
        Wi[u][3] = -cw[o + 1];
    }
    const float ct[4] = {1.f, 0.f, -1.f, 0.f};
    const float st[4] = {0.f, 1.f, 0.f, -1.f};
#pragma unroll
    for (int dp = 0; dp < 4; dp++)
#pragma unroll
        for (int dq = 0; dq < 4; dq++) {
            float s = 0.f;
#pragma unroll
            for (int u = 0; u < 4; u++)
#pragma unroll
                for (int v = 0; v < 4; v++) {
                    int m = (u * dp + v * dq) & 3;
                    s += Wr[u][v] * ct[m] - Wi[u][v] * st[m];
                }
            g_K[c * 16 + dp * 4 + dq] = s * (1.f / 16.f);
        }
}

// ---------------------------------------------------------------------------
// Warp-MMA helpers (sm_80-class PTX: valid on plain sm_103 target)
// ---------------------------------------------------------------------------
__device__ __forceinline__ uint32_t smem_u32(const void* p) {
    uint32_t a;
    asm("{ .reg .u64 t; cvta.to.shared.u64 t, %1; cvt.u32.u64 %0, t; }" : "=r"(a) : "l"(p));
    return a;
}
__device__ __forceinline__ void ldmx4(uint32_t* r, uint32_t addr) {
    asm volatile("ldmatrix.sync.aligned.m8n8.x4.shared.b16 {%0,%1,%2,%3}, [%4];"
        : "=r"(r[0]), "=r"(r[1]), "=r"(r[2]), "=r"(r[3]) : "r"(addr));
}
__device__ __forceinline__ void mma_f16(float* d, const uint32_t* a, const uint32_t* b) {
    asm volatile("mma.sync.aligned.m16n8k16.row.col.f32.f16.f16.f32 "
        "{%0,%1,%2,%3}, {%4,%5,%6,%7}, {%8,%9}, {%0,%1,%2,%3};"
        : "+f"(d[0]), "+f"(d[1]), "+f"(d[2]), "+f"(d[3])
        : "r"(a[0]), "r"(a[1]), "r"(a[2]), "r"(a[3]), "r"(b[0]), "r"(b[1]));
}

// XOR-swizzled byte offset inside a row-major smem tile (16B chunk permute).
__device__ __forceinline__ uint32_t swoff(uint32_t region, int row, int byte_col, int stride) {
    uint32_t b = (uint32_t)byte_col;
    return region + (uint32_t)(row * stride) + (b & 15u) + ((((b >> 4) ^ (uint32_t)(row & 7))) << 4);
}

__device__ __forceinline__ float gelu_exact(float h) {
    return 0.5f * h * (1.0f + erff(h * 0.70710678118654752f));
}
__device__ __forceinline__ uint32_t pack_h2(uint16_t e0, uint16_t e1) {
    return (uint32_t)e0 | ((uint32_t)e1 << 16);
}

// smem regions (bytes). Row-major fp16 tiles with XOR swizzle.
#define R_X     0u         // X  [128p][64k]   stride 128B, 16 KB
#define R_W1    16384u     // W1 [256j][64k]   stride 128B, 32 KB
#define R_W2    49152u     // W2 [64c][256j]   stride 512B, 32 KB
#define R_H     81920u     // H  [128p][128j]  stride 256B, 32 KB (per half)
#define R_B1    114688u    // 256 floats
#define R_B2    115712u    // 64 floats
#define SMEM_FFN 115968u

// ---------------------------------------------------------------------------
// Kernel 2: FFN via plain fp16 mma.sync GEMMs (fp32 accum). grid=148, 256 thr.
// GEMM1: D1[p,j] = X[p,k] W1[j,k]^T (K=64), two j-halves of 128
// GEMM2: D2[p,c] = H[p,j] W2[c,j]^T (K=256, accumulated over halves)
// fp16 rounding of x, W1, H, W2 -> rel_err ~4.5e-4 (deterministic inputs).
// ---------------------------------------------------------------------------
__global__ void __launch_bounds__(256, 1)
ffn_mma_kernel(const float* __restrict__ x,
               const float* __restrict__ w1,
               const float* __restrict__ b1,
               const float* __restrict__ w2,
               const float* __restrict__ b2) {
    extern __shared__ char smc[];
    const uint32_t sb = smem_u32(smc);
    const int tid = threadIdx.x;
    const int lane = tid & 31;
    const int wid = tid >> 5;
    const int wm = (wid & 3) * 32;
    const int wn = wid >> 2;

    // ---- one-time: weights -> fp16, swizzled smem ----
    {   // W1: thread = row j (256 rows x 64 k)
        const int j = tid;
        const float* wr = w1 + j * 64;
#pragma unroll
        for (int g = 0; g < 8; g++) {
            uint16_t hv[8];
#pragma unroll
            for (int e = 0; e < 8; e++) hv[e] = __half_as_ushort(__float2half_rn(wr[g * 8 + e]));
            *reinterpret_cast<uint4*>(smc + swoff(R_W1, j, g * 16, 128)) = *reinterpret_cast<uint4*>(hv);
        }
    }
    {   // W2: thread = (c row, j quarter)  (64 rows x 256 j)
        const int c = tid >> 2, jg = tid & 3;
        const float* wr = w2 + c * 256 + jg * 64;
#pragma unroll
        for (int g = 0; g < 8; g++) {
            uint16_t hv[8];
#pragma unroll
            for (int e = 0; e < 8; e++) hv[e] = __half_as_ushort(__float2half_rn(wr[g * 8 + e]));
            *reinterpret_cast<uint4*>(smc + swoff(R_W2, c, jg * 128 + g * 16, 512)) = *reinterpret_cast<uint4*>(hv);
        }
    }
    *reinterpret_cast<float*>(smc + R_B1 + tid * 4) = b1[tid];
    if (tid < 64) *reinterpret_cast<float*>(smc + R_B2 + tid * 4) = b2[tid];

    const float* b1s = reinterpret_cast<const float*>(smc + R_B1);
    const float* b2s = reinterpret_cast<const float*>(smc + R_B2);

    // ldmatrix per-lane address components (constant per thread)
    const int a_r = lane & 15;
    const int a_b = (lane >> 4) << 4;
    const int b_r = (lane & 7) + ((lane >> 4) << 3);
    const int b_b = ((lane >> 3) & 1) << 4;
    const int prow = lane >> 2;
    const int jcol = (lane & 3) * 2;

    for (int tile = blockIdx.x; tile < NTILES; tile += gridDim.x) {
        const int b = tile >> 9;
        const int pixbase = (tile & 511) << 7;

        // ---- stage X: float4 loads, fp16 round, swizzled store ----
        {
            const int ch = tid >> 2, q = tid & 3;
            const float* xp = x + ((size_t)b << 22) + ((size_t)ch << 16) + pixbase + q * 32;
#pragma unroll
            for (int i4 = 0; i4 < 8; i4++) {
                float4 v = reinterpret_cast<const float4*>(xp)[i4];
                const int r0 = q * 32 + i4 * 4;
                *reinterpret_cast<uint16_t*>(smc + swoff(R_X, r0,     ch * 2, 128)) = __half_as_ushort(__float2half_rn(v.x));
                *reinterpret_cast<uint16_t*>(smc + swoff(R_X, r0 + 1, ch * 2, 128)) = __half_as_ushort(__float2half_rn(v.y));
                *reinterpret_cast<uint16_t*>(smc + swoff(R_X, r0 + 2, ch * 2, 128)) = __half_as_ushort(__float2half_rn(v.z));
                *reinterpret_cast<uint16_t*>(smc + swoff(R_X, r0 + 3, ch * 2, 128)) = __half_as_ushort(__float2half_rn(v.w));
            }
        }
        __syncthreads();

        float acc2[2][4][4];
#pragma unroll
        for (int mt = 0; mt < 2; mt++)
#pragma unroll
            for (int nt = 0; nt < 4; nt++)
#pragma unroll
                for (int q = 0; q < 4; q++) acc2[mt][nt][q] = 0.f;

#pragma unroll 1
        for (int half = 0; half < 2; half++) {
            // ======== GEMM1: 32p x 64j per warp, K=64 ========
            float acc1[2][8][4];
#pragma unroll
            for (int mt = 0; mt < 2; mt++)
#pragma unroll
                for (int nt = 0; nt < 8; nt++)
#pragma unroll
                    for (int q = 0; q < 4; q++) acc1[mt][nt][q] = 0.f;

#pragma unroll 1
            for (int kt = 0; kt < 4; kt++) {
                uint32_t a0[4], a1[4];
                ldmx4(a0, sb + swoff(R_X, wm + a_r,      kt * 32 + a_b, 128));
                ldmx4(a1, sb + swoff(R_X, wm + 16 + a_r, kt * 32 + a_b, 128));
#pragma unroll
                for (int g = 0; g < 4; g++) {
                    const int n0 = half * 128 + wn * 64 + g * 16;
                    uint32_t bh[4];
                    ldmx4(bh, sb + swoff(R_W1, n0 + b_r, kt * 32 + b_b, 128));
                    mma_f16(acc1[0][2 * g],     a0, bh);
                    mma_f16(acc1[0][2 * g + 1], a0, bh + 2);
                    mma_f16(acc1[1][2 * g],     a1, bh);
                    mma_f16(acc1[1][2 * g + 1], a1, bh + 2);
                }
            }

            // ======== bias + GELU -> fp16 -> H smem ========
#pragma unroll
            for (int mt = 0; mt < 2; mt++)
#pragma unroll
                for (int nt = 0; nt < 8; nt++) {
                    const int p = wm + mt * 16 + prow;
                    const int j = wn * 64 + nt * 8 + jcol;
                    const float bj0 = b1s[half * 128 + j];
                    const float bj1 = b1s[half * 128 + j + 1];
                    float v0 = gelu_exact(acc1[mt][nt][0] + bj0);
                    float v1 = gelu_exact(acc1[mt][nt][1] + bj1);
                    float v2 = gelu_exact(acc1[mt][nt][2] + bj0);
                    float v3 = gelu_exact(acc1[mt][nt][3] + bj1);
                    uint16_t h0 = __half_as_ushort(__float2half_rn(v0));
                    uint16_t h1 = __half_as_ushort(__float2half_rn(v1));
                    uint16_t h2 = __half_as_ushort(__float2half_rn(v2));
                    uint16_t h3 = __half_as_ushort(__float2half_rn(v3));
                    *reinterpret_cast<uint32_t*>(smc + swoff(R_H, p,     j * 2, 256)) = pack_h2(h0, h1);
                    *reinterpret_cast<uint32_t*>(smc + swoff(R_H, p + 8, j * 2, 256)) = pack_h2(h2, h3);
                }
            __syncthreads();

            // ======== GEMM2: 32p x 32c per warp, K=128 this half ========
#pragma unroll 1
            for (int kt = 0; kt < 8; kt++) {
                uint32_t a0[4], a1[4];
                ldmx4(a0, sb + swoff(R_H, wm + a_r,      kt * 32 + a_b, 256));
                ldmx4(a1, sb + swoff(R_H, wm + 16 + a_r, kt * 32 + a_b, 256));
#pragma unroll
                for (int g = 0; g < 2; g++) {
                    const int n0 = wn * 32 + g * 16;
                    const int kb = half * 256 + kt * 32 + b_b;
                    uint32_t bh[4];
                    ldmx4(bh, sb + swoff(R_W2, n0 + b_r, kb, 512));
                    mma_f16(acc2[0][2 * g],     a0, bh);
                    mma_f16(acc2[0][2 * g + 1], a0, bh + 2);
                    mma_f16(acc2[1][2 * g],     a1, bh);
                    mma_f16(acc2[1][2 * g + 1], a1, bh + 2);
                }
            }
            __syncthreads();   // all warps done reading H before next overwrite
        }

        // ---- epilogue: +b2, write y ----
        float* yb = g_y + ((size_t)b << 22) + pixbase;
#pragma unroll
        for (int mt = 0; mt < 2; mt++)
#pragma unroll
            for (int nt = 0; nt < 4; nt++) {
                const int p = wm + mt * 16 + prow;
                const int c = wn * 32 + nt * 8 + jcol;
                yb[((size_t)c << 16) + p]           = acc2[mt][nt][0] + b2s[c];
                yb[((size_t)(c + 1) << 16) + p]     = acc2[mt][nt][1] + b2s[c + 1];
                yb[((size_t)c << 16) + p + 8]       = acc2[mt][nt][2] + b2s[c];
                yb[((size_t)(c + 1) << 16) + p + 8] = acc2[mt][nt][3] + b2s[c + 1];
            }
    }
}

// ---------------------------------------------------------------------------
// Kernel 3: per-window 4x4 circular convolution (unchanged).
// ---------------------------------------------------------------------------
__global__ void __launch_bounds__(256)
winconv_kernel(float* __restrict__ out) {
    const int idx = blockIdx.x * 256 + threadIdx.x;
    const int wx = idx & 63;
    const int wy = (idx >> 6) & 63;
    const int c  = (idx >> 12) & 63;
    const int b  = idx >> 18;

    __shared__ float Ks[16];
    if (threadIdx.x < 16) Ks[threadIdx.x] = g_K[(c << 4) + threadIdx.x];
    __syncthreads();

    float kr[16];
#pragma unroll
    for (int i = 0; i < 16; i++) kr[i] = Ks[i];

    const int base = (((b << 6) + c) << 16) + (wy << 2) * W_ + (wx << 2);
    const float* yp = g_y + base;

    float4 r0 = *reinterpret_cast<const float4*>(yp);
    float4 r1 = *reinterpret_cast<const float4*>(yp + W_);
    float4 r2 = *reinterpret_cast<const float4*>(yp + 2 * W_);
    float4 r3 = *reinterpret_cast<const float4*>(yp + 3 * W_);
    const float vv[16] = {r0.x, r0.y, r0.z, r0.w,
                          r1.x, r1.y, r1.z, r1.w,
                          r2.x, r2.y, r2.z, r2.w,
                          r3.x, r3.y, r3.z, r3.w};

#pragma unroll
    for (int ro = 0; ro < 4; ro++) {
        float o0 = 0.f, o1 = 0.f, o2 = 0.f, o3 = 0.f;
#pragma unroll
        for (int r = 0; r < 4; r++) {
            const int dp4 = ((ro - r) & 3) * 4;
#pragma unroll
            for (int s = 0; s < 4; s++) {
                const float v = vv[r * 4 + s];
                o0 = fmaf(kr[dp4 + ((0 - s) & 3)], v, o0);
                o1 = fmaf(kr[dp4 + ((1 - s) & 3)], v, o1);
                o2 = fmaf(kr[dp4 + ((2 - s) & 3)], v, o2);
                o3 = fmaf(kr[dp4 + ((3 - s) & 3)], v, o3);
            }
        }
        *reinterpret_cast<float4*>(out + base + ro * W_) = make_float4(o0, o1, o2, o3);
    }
}

// ---------------------------------------------------------------------------
extern "C" void kernel_launch(void* const* d_in, const int* in_sizes, int n_in,
                              void* d_out, int out_size) {
    const float* x  = (const float*)d_in[0];
    const float* w1 = (const float*)d_in[1];
    const float* b1 = (const float*)d_in[2];
    const float* w2 = (const float*)d_in[3];
    const float* b2 = (const float*)d_in[4];
    const float* cw = (const float*)d_in[5];
    float* out = (float*)d_out;

    cudaFuncSetAttribute(ffn_mma_kernel, cudaFuncAttributeMaxDynamicSharedMemorySize, SMEM_FFN);

    prep_K_kernel<<<1, 64>>>(cw);
    ffn_mma_kernel<<<148, 256, SMEM_FFN>>>(x, w1, b1, w2, b2);
    winconv_kernel<<<(B_ * C_ * (H_ / P_) * (W_ / P_)) / 256, 256>>>(out);
}